// round 4
// baseline (speedup 1.0000x reference)
#include <cuda_runtime.h>
#include <math.h>

#define N_CLS   3
#define N_YAW   2
#define NY      160
#define NX      160
#define N_ANCH  (N_YAW * NY * NX)   // 51200 anchor positions per class
#define N_BOX   32
#define CELLS_Y0 (NY * NX)          // 25600

// output layout (concatenated flattened float32 in return order)
#define OFF_GCLS 0
#define SZ_GCLS  (N_CLS * N_ANCH)
#define OFF_GREG (OFF_GCLS + SZ_GCLS)
#define SZ_GREG  (N_CLS * N_ANCH * 7)
#define OFF_MCLS (OFF_GREG + SZ_GREG)
#define SZ_MCLS  (N_ANCH)
#define OFF_MREG (OFF_MCLS + SZ_MCLS)
#define SZ_MREG  (N_CLS * CELLS_Y0)

// scratch: transposed IoU matrix g_iou4[k][position], k=0..7 selects boxes 4k..4k+3.
// Coalesced on both the producer and consumer side.
__device__ float4       g_iou4[(size_t)8 * N_ANCH];   // 6.5 MB
__device__ unsigned int g_high[N_BOX];

__constant__ float c_low[3]    = {0.45f, 0.35f, 0.35f};
__constant__ float c_highth[3] = {0.60f, 0.50f, 0.50f};

struct V2 { float x, y; };

// Intersection area of two rotated rectangles via Sutherland-Hodgman.
__device__ __forceinline__ float rect_inter_area(
    float cx1, float cy1, float hw1, float hl1, float c1, float s1,
    float cx2, float cy2, float hw2, float hl2, float c2, float s2)
{
    float ux2 = c2 * hw2, uy2 = s2 * hw2;
    float vx2 = -s2 * hl2, vy2 = c2 * hl2;
    V2 P[8], Q[8];
    P[0] = {cx2 + ux2 + vx2, cy2 + uy2 + vy2};
    P[1] = {cx2 + ux2 - vx2, cy2 + uy2 - vy2};
    P[2] = {cx2 - ux2 - vx2, cy2 - uy2 - vy2};
    P[3] = {cx2 - ux2 + vx2, cy2 - uy2 + vy2};
    int n = 4;

    float ux1 = c1 * hw1, uy1 = s1 * hw1;
    float vx1 = -s1 * hl1, vy1 = c1 * hl1;
    V2 CC[4];
    CC[0] = {cx1 + ux1 + vx1, cy1 + uy1 + vy1};
    CC[1] = {cx1 + ux1 - vx1, cy1 + uy1 - vy1};
    CC[2] = {cx1 - ux1 - vx1, cy1 - uy1 - vy1};
    CC[3] = {cx1 - ux1 + vx1, cy1 - uy1 + vy1};

    V2* src = P;
    V2* dst = Q;
    for (int e = 0; e < 4; e++) {
        V2 A = CC[e];
        V2 B = CC[(e + 1) & 3];
        float ex = B.x - A.x, ey = B.y - A.y;
        int m = 0;
        V2 pprev = src[n - 1];
        float dprev = ex * (pprev.y - A.y) - ey * (pprev.x - A.x);
        for (int i = 0; i < n; i++) {
            V2 p = src[i];
            float d = ex * (p.y - A.y) - ey * (p.x - A.x);
            bool inp = (d <= 0.0f), inprev = (dprev <= 0.0f);
            if (inprev != inp) {
                float t = dprev / (dprev - d);
                if (m < 8) { dst[m].x = pprev.x + t * (p.x - pprev.x);
                             dst[m].y = pprev.y + t * (p.y - pprev.y); m++; }
            }
            if (inp) { if (m < 8) dst[m++] = p; }
            dprev = d; pprev = p;
        }
        n = m;
        if (n == 0) return 0.0f;
        V2* tmp = src; src = dst; dst = tmp;
    }

    float ar = 0.0f;
    for (int i = 0; i < n; i++) {
        V2 p = src[i];
        V2 q = src[(i + 1 == n) ? 0 : (i + 1)];
        ar += p.x * q.y - q.x * p.y;
    }
    return 0.5f * fabsf(ar);
}

__global__ void iou_kernel(const float* __restrict__ boxes,
                           const float* __restrict__ anchors,
                           const int* __restrict__ cidx)
{
    __shared__ float sbx[N_BOX], sby[N_BOX], sbhw[N_BOX], sbhl[N_BOX],
                     sbc[N_BOX], sbs[N_BOX], sbr[N_BOX], sbar[N_BOX];
    __shared__ int   s_cls[N_BOX];

    const int tid = threadIdx.x;
    if (tid < N_BOX) {
        int b = tid;
        float x = boxes[b * 7 + 0];
        float y = boxes[b * 7 + 1];
        float w = boxes[b * 7 + 3];
        float l = boxes[b * 7 + 4];
        float yaw = boxes[b * 7 + 6];
        sbx[b] = x; sby[b] = y;
        sbhw[b] = 0.5f * w; sbhl[b] = 0.5f * l;
        sbc[b] = cosf(yaw); sbs[b] = sinf(yaw);
        sbr[b] = 0.5f * sqrtf(w * w + l * l);
        sbar[b] = w * l;
        s_cls[b] = cidx[b];
    }
    __syncthreads();

    // thread = (position, chunk of 8 boxes): 4x wider than one-thread-per-pos
    const int pos   = blockIdx.x * 64 + (tid & 63);
    const int chunk = tid >> 6;              // 0..3 -> boxes 8*chunk .. 8*chunk+7
    if (pos >= N_ANCH) return;

    const float* A0 = anchors + (size_t)pos * 7;
    float ax = A0[0], ay = A0[1], ayaw = A0[6];
    float ac = cosf(ayaw), as_ = sinf(ayaw);

    float ahw[3], ahl[3], arad[3], aarea[3];
    #pragma unroll
    for (int c = 0; c < N_CLS; c++) {
        const float* A = anchors + ((size_t)c * N_ANCH + pos) * 7;
        float w = A[3], l = A[4];
        ahw[c] = 0.5f * w; ahl[c] = 0.5f * l;
        arad[c] = 0.5f * sqrtf(w * w + l * l);
        aarea[c] = w * l;
    }

    float r[8];
    #pragma unroll
    for (int j = 0; j < 8; j++) {
        int b = chunk * 8 + j;
        int c = s_cls[b];
        float hw = (c == 0) ? ahw[0] : (c == 1) ? ahw[1] : ahw[2];
        float hl = (c == 0) ? ahl[0] : (c == 1) ? ahl[1] : ahl[2];
        float rad = (c == 0) ? arad[0] : (c == 1) ? arad[1] : arad[2];
        float area = (c == 0) ? aarea[0] : (c == 1) ? aarea[1] : aarea[2];

        float iou = 0.0f;
        float dx = sbx[b] - ax, dy = sby[b] - ay;
        float rr = sbr[b] + rad;
        if (dx * dx + dy * dy <= rr * rr) {
            float inter = rect_inter_area(
                sbx[b], sby[b], sbhw[b], sbhl[b], sbc[b], sbs[b],
                ax, ay, hw, hl, ac, as_);
            float uni = sbar[b] + area - inter;
            iou = inter / fmaxf(uni, 1e-8f);
            iou = fminf(fmaxf(iou, 0.0f), 1.0f);
            if (iou > 0.0f)
                atomicMax(&g_high[b], __float_as_uint(iou));
        }
        r[j] = iou;
    }

    // coalesced: consecutive pos -> consecutive float4
    g_iou4[(size_t)(chunk * 2 + 0) * N_ANCH + pos] = make_float4(r[0], r[1], r[2], r[3]);
    g_iou4[(size_t)(chunk * 2 + 1) * N_ANCH + pos] = make_float4(r[4], r[5], r[6], r[7]);
}

__global__ void combine_kernel(const float* __restrict__ boxes,
                               const float* __restrict__ anchors,
                               const int* __restrict__ cidx,
                               float* __restrict__ out)
{
    __shared__ int          c_cls[N_BOX];
    __shared__ unsigned int c_high[N_BOX];
    __shared__ float        c_box[N_BOX][7];
    __shared__ float        sreg[256 * 7];        // G_reg staging, 7 KB

    const int tid = threadIdx.x;
    if (tid < N_BOX) {
        int b = tid;
        c_cls[b] = cidx[b];
        c_high[b] = g_high[b];
        #pragma unroll
        for (int k = 0; k < 7; k++) c_box[b][k] = boxes[b * 7 + k];
    }
    __syncthreads();

    const int a = blockIdx.x * 256 + tid;

    // 8 coalesced 128-bit loads
    float iou[N_BOX];
    #pragma unroll
    for (int k = 0; k < 8; k++) {
        float4 v = g_iou4[(size_t)k * N_ANCH + a];
        iou[4 * k + 0] = v.x;
        iou[4 * k + 1] = v.y;
        iou[4 * k + 2] = v.z;
        iou[4 * k + 3] = v.w;
    }

    int lab[N_CLS], midx[N_CLS];
    #pragma unroll
    for (int c = 0; c < N_CLS; c++) {
        float maxv = -1.0f;   // reference masks non-class rows to -1
        int idx = 0;
        bool lq = false;
        #pragma unroll
        for (int b = 0; b < N_BOX; b++) {
            if (c_cls[b] == c) {          // uniform predicate
                float v = iou[b];
                if (v > maxv) { maxv = v; idx = b; }   // first-argmax
                if (v > 0.0f && __float_as_uint(v) == c_high[b]) lq = true;
            }
        }
        int L = (maxv >= c_highth[c]) ? 1 : ((maxv >= c_low[c]) ? -1 : 0);
        if (lq) L = 1;
        lab[c] = L;
        midx[c] = idx;
    }

    int pos = (lab[0] == 1) + (lab[1] == 1) + (lab[2] == 1);
    if (pos > 1) { lab[0] = -1; lab[1] = -1; lab[2] = -1; }
    bool neg = (lab[0] == 0) || (lab[1] == 0) || (lab[2] == 0);
    int pos2 = (lab[0] == 1) + (lab[1] == 1) + (lab[2] == 1);
    bool positive = (pos2 == 1);
    if (neg && !positive) { lab[0] = 0; lab[1] = 0; lab[2] = 0; }
    bool all_m1 = (lab[0] == -1) && (lab[1] == -1) && (lab[2] == -1);
    float loss_mask = all_m1 ? 0.0f : 1.0f;
    #pragma unroll
    for (int c = 0; c < N_CLS; c++)
        if (lab[c] == -1) lab[c] = 0;

    float* G_cls = out + OFF_GCLS;
    float* G_reg = out + OFF_GREG;
    float* M_cls = out + OFF_MCLS;
    float* M_reg = out + OFF_MREG;

    M_cls[a] = loss_mask;

    #pragma unroll
    for (int c = 0; c < N_CLS; c++) {
        G_cls[c * N_ANCH + a] = (float)lab[c];
        if (a < CELLS_Y0) M_reg[c * CELLS_Y0 + a] = (float)lab[c];
    }

    // G_reg: compute per-thread, stage in shared, stream out coalesced
    for (int c = 0; c < N_CLS; c++) {
        float vals[7] = {0.f, 0.f, 0.f, 0.f, 0.f, 0.f, 0.f};
        if (lab[c] == 1) {
            const float* B = c_box[midx[c]];
            const float* A = anchors + ((size_t)c * N_ANCH + a) * 7;
            float nrm = sqrtf(A[3] * A[3] + A[4] * A[4]);
            vals[0] = (B[0] - A[0]) / nrm;
            vals[1] = (B[1] - A[1]) / nrm;
            vals[2] = (B[2] - A[2]) / A[5];
            vals[3] = logf(B[3] / A[3]);
            vals[4] = logf(B[4] / A[4]);
            vals[5] = logf(B[5] / A[5]);
            vals[6] = B[6] - A[6];
        }
        #pragma unroll
        for (int k = 0; k < 7; k++) sreg[tid * 7 + k] = vals[k];   // stride 7: conflict-free
        __syncthreads();
        size_t base = ((size_t)c * N_ANCH + (size_t)blockIdx.x * 256) * 7;
        #pragma unroll
        for (int j = 0; j < 7; j++)
            G_reg[base + j * 256 + tid] = sreg[j * 256 + tid];     // coalesced
        __syncthreads();
    }
}

extern "C" void kernel_launch(void* const* d_in, const int* in_sizes, int n_in,
                              void* d_out, int out_size)
{
    const float* boxes = nullptr;
    const float* anchors = nullptr;
    const int* cidx = nullptr;
    for (int i = 0; i < n_in; i++) {
        if (in_sizes[i] == N_BOX * 7)               boxes = (const float*)d_in[i];
        else if (in_sizes[i] == N_CLS * N_ANCH * 7) anchors = (const float*)d_in[i];
        else if (in_sizes[i] == N_BOX)              cidx = (const int*)d_in[i];
    }
    float* out = (float*)d_out;

    void* high_ptr = nullptr;
    cudaGetSymbolAddress(&high_ptr, g_high);
    cudaMemsetAsync(high_ptr, 0, N_BOX * sizeof(unsigned int));

    iou_kernel<<<(N_ANCH + 63) / 64, 256>>>(boxes, anchors, cidx);
    combine_kernel<<<(N_ANCH + 255) / 256, 256>>>(boxes, anchors, cidx, out);
}